// round 1
// baseline (speedup 1.0000x reference)
#include <cuda_runtime.h>
#include <math.h>
#include <stdint.h>

// ---------------------------------------------------------------------------
// SpatioTemporalAttention: N=8, L=4096, C=1024, H=16, DH=64
//   queries = x_q @ Wq + bq
//   q_w     = softmax_L((queries @ Wqa + bqa) * 1/sqrt(DH))      per (n,h)
//   pooled_q[n,c] = sum_l q_w[n,h(c),l] * queries[n,l,c]
//   keys    = x_kv @ Wk + bk
//   k_w     = softmax_L(((keys * pooled_q) @ Wka + bka) / sqrt(DH))
//   pooled_k[n,c] = sum_l k_w[n,h(c),l] * keys[n,l,c]
//   tsum    = (values(=x_kv@Wv+bv) * pooled_k) @ Wt + bt + queries
//   out     = tsum @ Wp + bp
// ---------------------------------------------------------------------------

#define NB   8
#define LL   4096
#define CC   1024
#define HH   16
#define DH   64
#define MM   (NB*LL)      // 32768

// scratch (device globals; no runtime allocation allowed)
__device__ float g_queries[MM*CC];
__device__ float g_keys   [MM*CC];
__device__ float g_values [MM*CC];
__device__ float g_tsum   [MM*CC];
__device__ float g_logits [MM*HH];
__device__ float g_pq     [NB*CC];
__device__ float g_pk     [NB*CC];

__device__ __forceinline__ unsigned f2tf32(float x) {
    unsigned r;
    asm("cvt.rna.tf32.f32 %0, %1;" : "=r"(r) : "f"(x));
    return r;
}

__device__ __forceinline__ void mma_tf32(float c[4], const unsigned a[4], const unsigned b[2]) {
    asm volatile(
        "mma.sync.aligned.m16n8k8.row.col.f32.tf32.tf32.f32 "
        "{%0,%1,%2,%3}, {%4,%5,%6,%7}, {%8,%9}, {%0,%1,%2,%3};\n"
        : "+f"(c[0]), "+f"(c[1]), "+f"(c[2]), "+f"(c[3])
        : "r"(a[0]), "r"(a[1]), "r"(a[2]), "r"(a[3]), "r"(b[0]), "r"(b[1]));
}

// ---------------------------------------------------------------------------
// GEMM: out[M,1024] = (A .* gate?) @ W[1024,1024] + bias (+ addm)
// BM=128 BN=128 BK=32, 256 threads (8 warps, 2x4), warp tile 64x32,
// mma m16n8k8 tf32.
// gate: per (batch, k-channel) scalar applied to A on load (GATE).
// addm: elementwise matrix added in epilogue (ADD).
// ---------------------------------------------------------------------------
template<bool GATE, bool ADD>
__global__ void __launch_bounds__(256, 2) gemm_tf32_kernel(
    const float* __restrict__ A, const float* __restrict__ W,
    const float* __restrict__ bias, const float* __restrict__ gate,
    const float* __restrict__ addm, float* __restrict__ out)
{
    __shared__ unsigned As[128 * 36];   // stride 36 (16B-aligned rows, pad)
    __shared__ unsigned Bs[32 * 132];   // [k][n] stride 132

    const int tid  = threadIdx.x;
    const int bm   = blockIdx.y;
    const int bn   = blockIdx.x;
    const int warp = tid >> 5;
    const int lane = tid & 31;
    const int wm   = warp >> 2;     // 0..1
    const int wn   = warp & 3;      // 0..3
    const int nb   = (bm * 128) / LL;  // batch index (constant per block)

    float acc[4][4][4];
#pragma unroll
    for (int i = 0; i < 4; i++)
#pragma unroll
        for (int j = 0; j < 4; j++)
#pragma unroll
            for (int r = 0; r < 4; r++) acc[i][j][r] = 0.f;

    const int a_row0 = tid >> 3;           // + 32*i
    const int a_c4   = (tid & 7) * 4;
    const int b_kr0  = tid >> 5;           // + 8*i
    const int b_c4   = (tid & 31) * 4;

    for (int kb = 0; kb < CC; kb += 32) {
        // ---- load A tile [128 x 32] ----
#pragma unroll
        for (int i = 0; i < 4; i++) {
            const int r = a_row0 + 32 * i;
            float4 v = *(const float4*)(A + (size_t)(bm * 128 + r) * CC + kb + a_c4);
            if (GATE) {
                const float4 g = *(const float4*)(gate + nb * CC + kb + a_c4);
                v.x *= g.x; v.y *= g.y; v.z *= g.z; v.w *= g.w;
            }
            unsigned* p = &As[r * 36 + a_c4];
            p[0] = f2tf32(v.x); p[1] = f2tf32(v.y);
            p[2] = f2tf32(v.z); p[3] = f2tf32(v.w);
        }
        // ---- load B tile [32 x 128] ----
#pragma unroll
        for (int i = 0; i < 4; i++) {
            const int kr = b_kr0 + 8 * i;
            const float4 v = *(const float4*)(W + (size_t)(kb + kr) * CC + bn * 128 + b_c4);
            unsigned* p = &Bs[kr * 132 + b_c4];
            p[0] = f2tf32(v.x); p[1] = f2tf32(v.y);
            p[2] = f2tf32(v.z); p[3] = f2tf32(v.w);
        }
        __syncthreads();

#pragma unroll
        for (int ks = 0; ks < 4; ks++) {
            const int k0 = ks * 8;
            unsigned af[4][4], bf[4][2];
#pragma unroll
            for (int mt = 0; mt < 4; mt++) {
                const int row = wm * 64 + mt * 16 + (lane >> 2);
                const int col = k0 + (lane & 3);
                af[mt][0] = As[row * 36 + col];
                af[mt][1] = As[(row + 8) * 36 + col];
                af[mt][2] = As[row * 36 + col + 4];
                af[mt][3] = As[(row + 8) * 36 + col + 4];
            }
#pragma unroll
            for (int nt = 0; nt < 4; nt++) {
                const int coln = wn * 32 + nt * 8 + (lane >> 2);
                const int kk   = k0 + (lane & 3);
                bf[nt][0] = Bs[kk * 132 + coln];
                bf[nt][1] = Bs[(kk + 4) * 132 + coln];
            }
#pragma unroll
            for (int mt = 0; mt < 4; mt++)
#pragma unroll
                for (int nt = 0; nt < 4; nt++)
                    mma_tf32(acc[mt][nt], af[mt], bf[nt]);
        }
        __syncthreads();
    }

    // ---- epilogue ----
#pragma unroll
    for (int mt = 0; mt < 4; mt++) {
        const int r0 = bm * 128 + wm * 64 + mt * 16 + (lane >> 2);
#pragma unroll
        for (int nt = 0; nt < 4; nt++) {
            const int c0 = bn * 128 + wn * 32 + nt * 8 + (lane & 3) * 2;
            const float b0 = bias[c0], b1 = bias[c0 + 1];
            float v00 = acc[mt][nt][0] + b0;
            float v01 = acc[mt][nt][1] + b1;
            float v10 = acc[mt][nt][2] + b0;
            float v11 = acc[mt][nt][3] + b1;
            if (ADD) {
                v00 += addm[(size_t)r0 * CC + c0];
                v01 += addm[(size_t)r0 * CC + c0 + 1];
                v10 += addm[(size_t)(r0 + 8) * CC + c0];
                v11 += addm[(size_t)(r0 + 8) * CC + c0 + 1];
            }
            out[(size_t)r0 * CC + c0]           = v00;
            out[(size_t)r0 * CC + c0 + 1]       = v01;
            out[(size_t)(r0 + 8) * CC + c0]     = v10;
            out[(size_t)(r0 + 8) * CC + c0 + 1] = v11;
        }
    }
}

// ---------------------------------------------------------------------------
// logits[m, h] = ((X[m,:] .* gate?) @ Wa[:,h] + ba[h]) * 1/sqrt(DH)
// One warp per row, 8 warps per block.
// ---------------------------------------------------------------------------
template<bool GATE>
__global__ void logits_kernel(
    const float* __restrict__ X, const float* __restrict__ Wa,
    const float* __restrict__ ba, const float* __restrict__ gate,
    float* __restrict__ logits)
{
    const int warp = threadIdx.x >> 5;
    const int lane = threadIdx.x & 31;
    const int row  = blockIdx.x * 8 + warp;
    const int nb   = row / LL;

    float acc[HH];
#pragma unroll
    for (int h = 0; h < HH; h++) acc[h] = 0.f;

    for (int k = lane; k < CC; k += 32) {
        float xv = X[(size_t)row * CC + k];
        if (GATE) xv *= gate[nb * CC + k];
        const float4* wr = (const float4*)(Wa + (size_t)k * HH);
        const float4 w0 = wr[0], w1 = wr[1], w2 = wr[2], w3 = wr[3];
        acc[0]  += xv * w0.x; acc[1]  += xv * w0.y; acc[2]  += xv * w0.z; acc[3]  += xv * w0.w;
        acc[4]  += xv * w1.x; acc[5]  += xv * w1.y; acc[6]  += xv * w1.z; acc[7]  += xv * w1.w;
        acc[8]  += xv * w2.x; acc[9]  += xv * w2.y; acc[10] += xv * w2.z; acc[11] += xv * w2.w;
        acc[12] += xv * w3.x; acc[13] += xv * w3.y; acc[14] += xv * w3.z; acc[15] += xv * w3.w;
    }
#pragma unroll
    for (int h = 0; h < HH; h++) {
#pragma unroll
        for (int off = 16; off > 0; off >>= 1)
            acc[h] += __shfl_down_sync(0xffffffffu, acc[h], off);
    }
    if (lane == 0) {
        const float scale = 0.125f;  // 1/sqrt(64)
#pragma unroll
        for (int h = 0; h < HH; h++)
            logits[(size_t)row * HH + h] = (acc[h] + ba[h]) * scale;
    }
}

// ---------------------------------------------------------------------------
// Per (n,h): w = softmax_L(logits[n,:,h]);
//            pooled[n, h*64+d] = sum_l w[l] * X[n, l, h*64+d]
// One block per (n,h) pair; 256 threads.
// ---------------------------------------------------------------------------
__global__ void softmax_pool_kernel(
    const float* __restrict__ logits, const float* __restrict__ X,
    float* __restrict__ pooled)
{
    __shared__ float w[LL];
    __shared__ float red[256];

    const int n   = blockIdx.x >> 4;
    const int h   = blockIdx.x & 15;
    const int tid = threadIdx.x;

    float lmax = -INFINITY;
    for (int l = tid; l < LL; l += 256) {
        const float v = logits[(size_t)(n * LL + l) * HH + h];
        w[l] = v;
        lmax = fmaxf(lmax, v);
    }
    red[tid] = lmax;
    __syncthreads();
    for (int s = 128; s > 0; s >>= 1) {
        if (tid < s) red[tid] = fmaxf(red[tid], red[tid + s]);
        __syncthreads();
    }
    const float m = red[0];
    __syncthreads();

    float lsum = 0.f;
    for (int l = tid; l < LL; l += 256) {
        const float e = expf(w[l] - m);
        w[l] = e;
        lsum += e;
    }
    red[tid] = lsum;
    __syncthreads();
    for (int s = 128; s > 0; s >>= 1) {
        if (tid < s) red[tid] += red[tid + s];
        __syncthreads();
    }
    const float inv = 1.0f / red[0];
    __syncthreads();

    const int d = tid & 63;
    const int g = tid >> 6;     // 4 l-groups
    float acc = 0.f;
    for (int l = g; l < LL; l += 4)
        acc += w[l] * X[(size_t)(n * LL + l) * CC + h * DH + d];

    red[tid] = acc;
    __syncthreads();
    if (tid < 64)
        pooled[n * CC + h * DH + d] =
            (red[d] + red[64 + d] + red[128 + d] + red[192 + d]) * inv;
}

// ---------------------------------------------------------------------------
extern "C" void kernel_launch(void* const* d_in, const int* in_sizes, int n_in,
                              void* d_out, int out_size)
{
    const float* x_q  = (const float*)d_in[0];
    const float* x_kv = (const float*)d_in[1];
    const float* Wq   = (const float*)d_in[2];
    const float* bq   = (const float*)d_in[3];
    const float* Wqa  = (const float*)d_in[4];
    const float* bqa  = (const float*)d_in[5];
    const float* Wk   = (const float*)d_in[6];
    const float* bk   = (const float*)d_in[7];
    const float* Wka  = (const float*)d_in[8];
    const float* bka  = (const float*)d_in[9];
    const float* Wv   = (const float*)d_in[10];
    const float* bv   = (const float*)d_in[11];
    const float* Wt   = (const float*)d_in[12];
    const float* bt   = (const float*)d_in[13];
    const float* Wp   = (const float*)d_in[14];
    const float* bp   = (const float*)d_in[15];
    float* out = (float*)d_out;

    float *queries, *keys, *values, *tsum, *logits, *pq, *pk;
    cudaGetSymbolAddress((void**)&queries, g_queries);
    cudaGetSymbolAddress((void**)&keys,    g_keys);
    cudaGetSymbolAddress((void**)&values,  g_values);
    cudaGetSymbolAddress((void**)&tsum,    g_tsum);
    cudaGetSymbolAddress((void**)&logits,  g_logits);
    cudaGetSymbolAddress((void**)&pq,      g_pq);
    cudaGetSymbolAddress((void**)&pk,      g_pk);

    const dim3 ggrid(CC / 128, MM / 128);   // (8, 256)
    const dim3 gblk(256);

    // queries = x_q @ Wq + bq
    gemm_tf32_kernel<false, false><<<ggrid, gblk>>>(x_q, Wq, bq, nullptr, nullptr, queries);
    // q logits + softmax-pool -> pooled_q
    logits_kernel<false><<<MM / 8, 256>>>(queries, Wqa, bqa, nullptr, logits);
    softmax_pool_kernel<<<NB * HH, 256>>>(logits, queries, pq);
    // keys = x_kv @ Wk + bk
    gemm_tf32_kernel<false, false><<<ggrid, gblk>>>(x_kv, Wk, bk, nullptr, nullptr, keys);
    // k logits (keys gated by pooled_q) + softmax-pool -> pooled_k
    logits_kernel<true><<<MM / 8, 256>>>(keys, Wka, bka, pq, logits);
    softmax_pool_kernel<<<NB * HH, 256>>>(logits, keys, pk);
    // values = x_kv @ Wv + bv
    gemm_tf32_kernel<false, false><<<ggrid, gblk>>>(x_kv, Wv, bv, nullptr, nullptr, values);
    // tsum = (values .* pooled_k) @ Wt + bt + queries
    gemm_tf32_kernel<true, true><<<ggrid, gblk>>>(values, Wt, bt, pk, queries, tsum);
    // out = tsum @ Wp + bp
    gemm_tf32_kernel<false, false><<<ggrid, gblk>>>(tsum, Wp, bp, nullptr, nullptr, out);
}

// round 2
// speedup vs baseline: 1.0001x; 1.0001x over previous
#include <cuda_runtime.h>
#include <math.h>
#include <stdint.h>

// ---------------------------------------------------------------------------
// SpatioTemporalAttention: N=8, L=4096, C=1024, H=16, DH=64
//   queries = x_q @ Wq + bq
//   q_w     = softmax_L((queries @ Wqa + bqa) * 1/sqrt(DH))      per (n,h)
//   pooled_q[n,c] = sum_l q_w[n,h(c),l] * queries[n,l,c]
//   keys    = x_kv @ Wk + bk
//   k_w     = softmax_L(((keys * pooled_q) @ Wka + bka) / sqrt(DH))
//   pooled_k[n,c] = sum_l k_w[n,h(c),l] * keys[n,l,c]
//   tsum    = (values(=x_kv@Wv+bv) * pooled_k) @ Wt + bt + queries
//   out     = tsum @ Wp + bp
// ---------------------------------------------------------------------------

#define NB   8
#define LL   4096
#define CC   1024
#define HH   16
#define DH   64
#define MM   (NB*LL)      // 32768

// scratch (device globals; no runtime allocation allowed)
__device__ float g_queries[MM*CC];
__device__ float g_keys   [MM*CC];
__device__ float g_values [MM*CC];
__device__ float g_tsum   [MM*CC];
__device__ float g_logits [MM*HH];
__device__ float g_pq     [NB*CC];
__device__ float g_pk     [NB*CC];

__device__ __forceinline__ unsigned f2tf32(float x) {
    unsigned r;
    asm("cvt.rna.tf32.f32 %0, %1;" : "=r"(r) : "f"(x));
    return r;
}

__device__ __forceinline__ void mma_tf32(float c[4], const unsigned a[4], const unsigned b[2]) {
    asm volatile(
        "mma.sync.aligned.m16n8k8.row.col.f32.tf32.tf32.f32 "
        "{%0,%1,%2,%3}, {%4,%5,%6,%7}, {%8,%9}, {%0,%1,%2,%3};\n"
        : "+f"(c[0]), "+f"(c[1]), "+f"(c[2]), "+f"(c[3])
        : "r"(a[0]), "r"(a[1]), "r"(a[2]), "r"(a[3]), "r"(b[0]), "r"(b[1]));
}

// ---------------------------------------------------------------------------
// GEMM: out[M,1024] = (A .* gate?) @ W[1024,1024] + bias (+ addm)
// BM=128 BN=128 BK=32, 256 threads (8 warps, 2x4), warp tile 64x32,
// mma m16n8k8 tf32.
// gate: per (batch, k-channel) scalar applied to A on load (GATE).
// addm: elementwise matrix added in epilogue (ADD).
// ---------------------------------------------------------------------------
template<bool GATE, bool ADD>
__global__ void __launch_bounds__(256, 2) gemm_tf32_kernel(
    const float* __restrict__ A, const float* __restrict__ W,
    const float* __restrict__ bias, const float* __restrict__ gate,
    const float* __restrict__ addm, float* __restrict__ out)
{
    __shared__ unsigned As[128 * 36];   // stride 36 (16B-aligned rows, pad)
    __shared__ unsigned Bs[32 * 132];   // [k][n] stride 132

    const int tid  = threadIdx.x;
    const int bm   = blockIdx.y;
    const int bn   = blockIdx.x;
    const int warp = tid >> 5;
    const int lane = tid & 31;
    const int wm   = warp >> 2;     // 0..1
    const int wn   = warp & 3;      // 0..3
    const int nb   = (bm * 128) / LL;  // batch index (constant per block)

    float acc[4][4][4];
#pragma unroll
    for (int i = 0; i < 4; i++)
#pragma unroll
        for (int j = 0; j < 4; j++)
#pragma unroll
            for (int r = 0; r < 4; r++) acc[i][j][r] = 0.f;

    const int a_row0 = tid >> 3;           // + 32*i
    const int a_c4   = (tid & 7) * 4;
    const int b_kr0  = tid >> 5;           // + 8*i
    const int b_c4   = (tid & 31) * 4;

    for (int kb = 0; kb < CC; kb += 32) {
        // ---- load A tile [128 x 32] ----
#pragma unroll
        for (int i = 0; i < 4; i++) {
            const int r = a_row0 + 32 * i;
            float4 v = *(const float4*)(A + (size_t)(bm * 128 + r) * CC + kb + a_c4);
            if (GATE) {
                const float4 g = *(const float4*)(gate + nb * CC + kb + a_c4);
                v.x *= g.x; v.y *= g.y; v.z *= g.z; v.w *= g.w;
            }
            unsigned* p = &As[r * 36 + a_c4];
            p[0] = f2tf32(v.x); p[1] = f2tf32(v.y);
            p[2] = f2tf32(v.z); p[3] = f2tf32(v.w);
        }
        // ---- load B tile [32 x 128] ----
#pragma unroll
        for (int i = 0; i < 4; i++) {
            const int kr = b_kr0 + 8 * i;
            const float4 v = *(const float4*)(W + (size_t)(kb + kr) * CC + bn * 128 + b_c4);
            unsigned* p = &Bs[kr * 132 + b_c4];
            p[0] = f2tf32(v.x); p[1] = f2tf32(v.y);
            p[2] = f2tf32(v.z); p[3] = f2tf32(v.w);
        }
        __syncthreads();

#pragma unroll
        for (int ks = 0; ks < 4; ks++) {
            const int k0 = ks * 8;
            unsigned af[4][4], bf[4][2];
#pragma unroll
            for (int mt = 0; mt < 4; mt++) {
                const int row = wm * 64 + mt * 16 + (lane >> 2);
                const int col = k0 + (lane & 3);
                af[mt][0] = As[row * 36 + col];
                af[mt][1] = As[(row + 8) * 36 + col];
                af[mt][2] = As[row * 36 + col + 4];
                af[mt][3] = As[(row + 8) * 36 + col + 4];
            }
#pragma unroll
            for (int nt = 0; nt < 4; nt++) {
                const int coln = wn * 32 + nt * 8 + (lane >> 2);
                const int kk   = k0 + (lane & 3);
                bf[nt][0] = Bs[kk * 132 + coln];
                bf[nt][1] = Bs[(kk + 4) * 132 + coln];
            }
#pragma unroll
            for (int mt = 0; mt < 4; mt++)
#pragma unroll
                for (int nt = 0; nt < 4; nt++)
                    mma_tf32(acc[mt][nt], af[mt], bf[nt]);
        }
        __syncthreads();
    }

    // ---- epilogue ----
#pragma unroll
    for (int mt = 0; mt < 4; mt++) {
        const int r0 = bm * 128 + wm * 64 + mt * 16 + (lane >> 2);
#pragma unroll
        for (int nt = 0; nt < 4; nt++) {
            const int c0 = bn * 128 + wn * 32 + nt * 8 + (lane & 3) * 2;
            const float b0 = bias[c0], b1 = bias[c0 + 1];
            float v00 = acc[mt][nt][0] + b0;
            float v01 = acc[mt][nt][1] + b1;
            float v10 = acc[mt][nt][2] + b0;
            float v11 = acc[mt][nt][3] + b1;
            if (ADD) {
                v00 += addm[(size_t)r0 * CC + c0];
                v01 += addm[(size_t)r0 * CC + c0 + 1];
                v10 += addm[(size_t)(r0 + 8) * CC + c0];
                v11 += addm[(size_t)(r0 + 8) * CC + c0 + 1];
            }
            out[(size_t)r0 * CC + c0]           = v00;
            out[(size_t)r0 * CC + c0 + 1]       = v01;
            out[(size_t)(r0 + 8) * CC + c0]     = v10;
            out[(size_t)(r0 + 8) * CC + c0 + 1] = v11;
        }
    }
}

// ---------------------------------------------------------------------------
// logits[m, h] = ((X[m,:] .* gate?) @ Wa[:,h] + ba[h]) * 1/sqrt(DH)
// One warp per row, 8 warps per block.
// ---------------------------------------------------------------------------
template<bool GATE>
__global__ void logits_kernel(
    const float* __restrict__ X, const float* __restrict__ Wa,
    const float* __restrict__ ba, const float* __restrict__ gate,
    float* __restrict__ logits)
{
    const int warp = threadIdx.x >> 5;
    const int lane = threadIdx.x & 31;
    const int row  = blockIdx.x * 8 + warp;
    const int nb   = row / LL;

    float acc[HH];
#pragma unroll
    for (int h = 0; h < HH; h++) acc[h] = 0.f;

    for (int k = lane; k < CC; k += 32) {
        float xv = X[(size_t)row * CC + k];
        if (GATE) xv *= gate[nb * CC + k];
        const float4* wr = (const float4*)(Wa + (size_t)k * HH);
        const float4 w0 = wr[0], w1 = wr[1], w2 = wr[2], w3 = wr[3];
        acc[0]  += xv * w0.x; acc[1]  += xv * w0.y; acc[2]  += xv * w0.z; acc[3]  += xv * w0.w;
        acc[4]  += xv * w1.x; acc[5]  += xv * w1.y; acc[6]  += xv * w1.z; acc[7]  += xv * w1.w;
        acc[8]  += xv * w2.x; acc[9]  += xv * w2.y; acc[10] += xv * w2.z; acc[11] += xv * w2.w;
        acc[12] += xv * w3.x; acc[13] += xv * w3.y; acc[14] += xv * w3.z; acc[15] += xv * w3.w;
    }
#pragma unroll
    for (int h = 0; h < HH; h++) {
#pragma unroll
        for (int off = 16; off > 0; off >>= 1)
            acc[h] += __shfl_down_sync(0xffffffffu, acc[h], off);
    }
    if (lane == 0) {
        const float scale = 0.125f;  // 1/sqrt(64)
#pragma unroll
        for (int h = 0; h < HH; h++)
            logits[(size_t)row * HH + h] = (acc[h] + ba[h]) * scale;
    }
}

// ---------------------------------------------------------------------------
// Per (n,h): w = softmax_L(logits[n,:,h]);
//            pooled[n, h*64+d] = sum_l w[l] * X[n, l, h*64+d]
// One block per (n,h) pair; 256 threads.
// ---------------------------------------------------------------------------
__global__ void softmax_pool_kernel(
    const float* __restrict__ logits, const float* __restrict__ X,
    float* __restrict__ pooled)
{
    __shared__ float w[LL];
    __shared__ float red[256];

    const int n   = blockIdx.x >> 4;
    const int h   = blockIdx.x & 15;
    const int tid = threadIdx.x;

    float lmax = -INFINITY;
    for (int l = tid; l < LL; l += 256) {
        const float v = logits[(size_t)(n * LL + l) * HH + h];
        w[l] = v;
        lmax = fmaxf(lmax, v);
    }
    red[tid] = lmax;
    __syncthreads();
    for (int s = 128; s > 0; s >>= 1) {
        if (tid < s) red[tid] = fmaxf(red[tid], red[tid + s]);
        __syncthreads();
    }
    const float m = red[0];
    __syncthreads();

    float lsum = 0.f;
    for (int l = tid; l < LL; l += 256) {
        const float e = expf(w[l] - m);
        w[l] = e;
        lsum += e;
    }
    red[tid] = lsum;
    __syncthreads();
    for (int s = 128; s > 0; s >>= 1) {
        if (tid < s) red[tid] += red[tid + s];
        __syncthreads();
    }
    const float inv = 1.0f / red[0];
    __syncthreads();

    const int d = tid & 63;
    const int g = tid >> 6;     // 4 l-groups
    float acc = 0.f;
    for (int l = g; l < LL; l += 4)
        acc += w[l] * X[(size_t)(n * LL + l) * CC + h * DH + d];

    red[tid] = acc;
    __syncthreads();
    if (tid < 64)
        pooled[n * CC + h * DH + d] =
            (red[d] + red[64 + d] + red[128 + d] + red[192 + d]) * inv;
}

// ---------------------------------------------------------------------------
extern "C" void kernel_launch(void* const* d_in, const int* in_sizes, int n_in,
                              void* d_out, int out_size)
{
    const float* x_q  = (const float*)d_in[0];
    const float* x_kv = (const float*)d_in[1];
    const float* Wq   = (const float*)d_in[2];
    const float* bq   = (const float*)d_in[3];
    const float* Wqa  = (const float*)d_in[4];
    const float* bqa  = (const float*)d_in[5];
    const float* Wk   = (const float*)d_in[6];
    const float* bk   = (const float*)d_in[7];
    const float* Wka  = (const float*)d_in[8];
    const float* bka  = (const float*)d_in[9];
    const float* Wv   = (const float*)d_in[10];
    const float* bv   = (const float*)d_in[11];
    const float* Wt   = (const float*)d_in[12];
    const float* bt   = (const float*)d_in[13];
    const float* Wp   = (const float*)d_in[14];
    const float* bp   = (const float*)d_in[15];
    float* out = (float*)d_out;

    float *queries, *keys, *values, *tsum, *logits, *pq, *pk;
    cudaGetSymbolAddress((void**)&queries, g_queries);
    cudaGetSymbolAddress((void**)&keys,    g_keys);
    cudaGetSymbolAddress((void**)&values,  g_values);
    cudaGetSymbolAddress((void**)&tsum,    g_tsum);
    cudaGetSymbolAddress((void**)&logits,  g_logits);
    cudaGetSymbolAddress((void**)&pq,      g_pq);
    cudaGetSymbolAddress((void**)&pk,      g_pk);

    const dim3 ggrid(CC / 128, MM / 128);   // (8, 256)
    const dim3 gblk(256);

    // queries = x_q @ Wq + bq
    gemm_tf32_kernel<false, false><<<ggrid, gblk>>>(x_q, Wq, bq, nullptr, nullptr, queries);
    // q logits + softmax-pool -> pooled_q
    logits_kernel<false><<<MM / 8, 256>>>(queries, Wqa, bqa, nullptr, logits);
    softmax_pool_kernel<<<NB * HH, 256>>>(logits, queries, pq);
    // keys = x_kv @ Wk + bk
    gemm_tf32_kernel<false, false><<<ggrid, gblk>>>(x_kv, Wk, bk, nullptr, nullptr, keys);
    // k logits (keys gated by pooled_q) + softmax-pool -> pooled_k
    logits_kernel<true><<<MM / 8, 256>>>(keys, Wka, bka, pq, logits);
    softmax_pool_kernel<<<NB * HH, 256>>>(logits, keys, pk);
    // values = x_kv @ Wv + bv
    gemm_tf32_kernel<false, false><<<ggrid, gblk>>>(x_kv, Wv, bv, nullptr, nullptr, values);
    // tsum = (values .* pooled_k) @ Wt + bt + queries
    gemm_tf32_kernel<true, true><<<ggrid, gblk>>>(values, Wt, bt, pk, queries, tsum);
    // out = tsum @ Wp + bp
    gemm_tf32_kernel<false, false><<<ggrid, gblk>>>(tsum, Wp, bp, nullptr, nullptr, out);
}